// round 1
// baseline (speedup 1.0000x reference)
#include <cuda_runtime.h>
#include <cuda_bf16.h>
#include <math.h>
#include <stdint.h>

// Problem constants
#define D 256
#define NH 8
#define HD 32
#define LEV 3
#define NP 4
#define DFF 1024
#define BATCH 8
#define LQ 3600
#define M_ROWS (LQ * BATCH)       // 28800, row r = l*8 + b
#define LIN 4725
#define MV_ROWS (BATCH * LIN)     // 37800

// ---------------- scratch (device globals; allocation-free) ----------------
__device__ float g_QKV[M_ROWS * 3 * D];   // 88.5 MB
__device__ float g_CTX[M_ROWS * D];
__device__ float g_T[M_ROWS * D];
__device__ float g_TGT2[M_ROWS * D];
__device__ float g_OFF[M_ROWS * NH * LEV * NP * 2];
__device__ float g_AW[M_ROWS * NH * LEV * NP];
__device__ float g_VALUE[MV_ROWS * D];
__device__ float g_SAMP[M_ROWS * D];
__device__ float g_TQ[M_ROWS * D];
__device__ float g_HID[M_ROWS * DFF];     // 118 MB
__device__ float g_BIAS[768 + 192 + 96];  // pos-folded biases

// ---------------- bias folding: b' = b + pos @ W^T ----------------
__global__ void bias_fold_kernel(const float* __restrict__ pos,
                                 const float* __restrict__ Wqkv, const float* __restrict__ bqkv,
                                 const float* __restrict__ Wso,  const float* __restrict__ bso,
                                 const float* __restrict__ Waw,  const float* __restrict__ baw) {
    int i = blockIdx.x, t = threadIdx.x;
    const float* wrow = nullptr; float bb;
    if (i < 768)      { bb = bqkv[i]; if (i < 512) wrow = Wqkv + (size_t)i * D; }  // v bias unchanged
    else if (i < 960) { int j = i - 768; bb = bso[j]; wrow = Wso + (size_t)j * D; }
    else              { int j = i - 960; bb = baw[j]; wrow = Waw + (size_t)j * D; }
    float p = wrow ? pos[t] * wrow[t] : 0.f;
    #pragma unroll
    for (int m = 16; m; m >>= 1) p += __shfl_xor_sync(0xffffffffu, p, m);
    __shared__ float sh[8];
    if ((t & 31) == 0) sh[t >> 5] = p;
    __syncthreads();
    if (t == 0) {
        float s = 0.f;
        #pragma unroll
        for (int w = 0; w < 8; w++) s += sh[w];
        g_BIAS[i] = bb + s;
    }
}

// ---------------- SGEMM: C[M,N] = A[M,K] @ W[N,K]^T + bias, opt ReLU -------
// 128x128 tile, BK=8, 256 threads, 8x8 per thread.
__global__ __launch_bounds__(256)
void sgemm_bias_kernel(const float* __restrict__ A, const float* __restrict__ W,
                       const float* __restrict__ bias, float* __restrict__ C,
                       int M, int N, int K, int relu) {
    __shared__ float As[8][128];
    __shared__ float Ws[8][128];
    int tid = threadIdx.x;
    int m0 = blockIdx.y * 128, n0 = blockIdx.x * 128;
    int tx = tid & 15, ty = tid >> 4;
    int lrow = tid >> 1;
    int lk4  = (tid & 1) * 4;
    float acc[8][8];
    #pragma unroll
    for (int i = 0; i < 8; i++)
        #pragma unroll
        for (int j = 0; j < 8; j++) acc[i][j] = 0.f;

    for (int k0 = 0; k0 < K; k0 += 8) {
        float4 av = make_float4(0.f, 0.f, 0.f, 0.f);
        int am = m0 + lrow;
        if (am < M) av = *reinterpret_cast<const float4*>(&A[(size_t)am * K + k0 + lk4]);
        As[lk4 + 0][lrow] = av.x; As[lk4 + 1][lrow] = av.y;
        As[lk4 + 2][lrow] = av.z; As[lk4 + 3][lrow] = av.w;
        float4 wv = make_float4(0.f, 0.f, 0.f, 0.f);
        int wn = n0 + lrow;
        if (wn < N) wv = *reinterpret_cast<const float4*>(&W[(size_t)wn * K + k0 + lk4]);
        Ws[lk4 + 0][lrow] = wv.x; Ws[lk4 + 1][lrow] = wv.y;
        Ws[lk4 + 2][lrow] = wv.z; Ws[lk4 + 3][lrow] = wv.w;
        __syncthreads();
        #pragma unroll
        for (int kk = 0; kk < 8; kk++) {
            float ar[8], br[8];
            #pragma unroll
            for (int i = 0; i < 8; i++) ar[i] = As[kk][ty * 8 + i];
            #pragma unroll
            for (int j = 0; j < 8; j++) br[j] = Ws[kk][tx * 8 + j];
            #pragma unroll
            for (int i = 0; i < 8; i++)
                #pragma unroll
                for (int j = 0; j < 8; j++) acc[i][j] += ar[i] * br[j];
        }
        __syncthreads();
    }
    #pragma unroll
    for (int i = 0; i < 8; i++) {
        int m = m0 + ty * 8 + i;
        if (m >= M) break;
        #pragma unroll
        for (int j = 0; j < 8; j++) {
            int n = n0 + tx * 8 + j;
            if (n < N) {
                float v = acc[i][j] + bias[n];
                if (relu) v = fmaxf(v, 0.f);
                C[(size_t)m * N + n] = v;
            }
        }
    }
}

// ---------------- tiny self-attention over S=8 (batch-as-sequence) --------
// block = query index n (0..3599), warp = head, lane = channel d.
__global__ __launch_bounds__(256)
void self_attn_kernel(const float* __restrict__ QKV, float* __restrict__ CTX) {
    int n = blockIdx.x;
    int h = threadIdx.x >> 5, lane = threadIdx.x & 31;
    const float* base = QKV + (size_t)n * 8 * (3 * D) + h * HD + lane;
    float q[8], k[8], v[8];
    #pragma unroll
    for (int s = 0; s < 8; s++) {
        q[s] = base[s * 3 * D];
        k[s] = base[s * 3 * D + D];
        v[s] = base[s * 3 * D + 2 * D];
    }
    const float scale = rsqrtf((float)HD);
    #pragma unroll
    for (int s = 0; s < 8; s++) {
        float lg[8];
        #pragma unroll
        for (int t = 0; t < 8; t++) {
            float p = q[s] * k[t];
            #pragma unroll
            for (int m = 16; m; m >>= 1) p += __shfl_xor_sync(0xffffffffu, p, m);
            lg[t] = p * scale;
        }
        float mx = lg[0];
        #pragma unroll
        for (int t = 1; t < 8; t++) mx = fmaxf(mx, lg[t]);
        float sum = 0.f, e[8];
        #pragma unroll
        for (int t = 0; t < 8; t++) { e[t] = __expf(lg[t] - mx); sum += e[t]; }
        float inv = 1.f / sum;
        float c = 0.f;
        #pragma unroll
        for (int t = 0; t < 8; t++) c += e[t] * v[t];
        c *= inv;
        CTX[(size_t)(n * 8 + s) * D + h * HD + lane] = c;
    }
}

// ---------------- residual + LayerNorm ----------------
__global__ __launch_bounds__(256)
void add_ln_kernel(const float* __restrict__ A, const float* __restrict__ Bv,
                   const float* __restrict__ g, const float* __restrict__ be,
                   float* __restrict__ out) {
    int r = blockIdx.x, d = threadIdx.x;
    size_t idx = (size_t)r * D + d;
    float x = A[idx] + Bv[idx];
    __shared__ float sh[8];
    __shared__ float s_mean, s_var;
    float p = x;
    #pragma unroll
    for (int m = 16; m; m >>= 1) p += __shfl_xor_sync(0xffffffffu, p, m);
    if ((d & 31) == 0) sh[d >> 5] = p;
    __syncthreads();
    if (d == 0) {
        float s = 0.f;
        #pragma unroll
        for (int w = 0; w < 8; w++) s += sh[w];
        s_mean = s * (1.f / D);
    }
    __syncthreads();
    float xm = x - s_mean;
    p = xm * xm;
    #pragma unroll
    for (int m = 16; m; m >>= 1) p += __shfl_xor_sync(0xffffffffu, p, m);
    __syncthreads();  // protect sh reuse
    if ((d & 31) == 0) sh[d >> 5] = p;
    __syncthreads();
    if (d == 0) {
        float s = 0.f;
        #pragma unroll
        for (int w = 0; w < 8; w++) s += sh[w];
        s_var = s * (1.f / D);
    }
    __syncthreads();
    out[idx] = xm * rsqrtf(s_var + 1e-5f) * g[d] + be[d];
}

// ---------------- MS-deformable sampling (fused aw-softmax) ----------------
// grid = 28800 rows, block 256: warp = head, lane = channel within head.
__global__ __launch_bounds__(256)
void msdeform_sample_kernel(const float* __restrict__ OFF, const float* __restrict__ AW,
                            const float* __restrict__ VALUE, float* __restrict__ SAMP) {
    int r = blockIdx.x;
    int h = threadIdx.x >> 5, lane = threadIdx.x & 31;
    int l = r >> 3, b = r & 7;
    float refx = ((float)(l % 60) + 0.5f) / 60.f;
    float refy = ((float)(l / 60) + 0.5f) / 60.f;

    // softmax over 12 attention logits for this (r, h)
    const float* awp = AW + (size_t)r * (NH * LEV * NP) + h * (LEV * NP);
    float w[LEV * NP];
    float mx = -1e30f;
    #pragma unroll
    for (int i = 0; i < LEV * NP; i++) { w[i] = awp[i]; mx = fmaxf(mx, w[i]); }
    float s = 0.f;
    #pragma unroll
    for (int i = 0; i < LEV * NP; i++) { w[i] = __expf(w[i] - mx); s += w[i]; }
    float inv = 1.f / s;

    const float* offp = OFF + (size_t)r * (NH * LEV * NP * 2) + h * (LEV * NP * 2);
    const int Hs[LEV] = {60, 30, 15};
    const int Ss[LEV] = {0, 3600, 4500};

    float acc = 0.f;
    #pragma unroll
    for (int lev = 0; lev < LEV; lev++) {
        const int Hl = Hs[lev], Wl = Hs[lev];
        const float* vbase = VALUE + ((size_t)b * LIN + Ss[lev]) * D + h * HD + lane;
        #pragma unroll
        for (int p = 0; p < NP; p++) {
            float ox = offp[lev * (NP * 2) + p * 2 + 0];
            float oy = offp[lev * (NP * 2) + p * 2 + 1];
            float lx = refx + ox / (float)Wl;
            float ly = refy + oy / (float)Hl;
            float x = lx * (float)Wl - 0.5f;
            float y = ly * (float)Hl - 0.5f;
            float x0f = floorf(x), y0f = floorf(y);
            float fx = x - x0f, fy = y - y0f;
            int x0 = (int)x0f, y0 = (int)y0f;
            float aww = w[lev * NP + p] * inv;
            float gsum = 0.f;
            #pragma unroll
            for (int cy = 0; cy < 2; cy++) {
                #pragma unroll
                for (int cx = 0; cx < 2; cx++) {
                    int xi = x0 + cx, yi = y0 + cy;
                    float cw = (cx ? fx : 1.f - fx) * (cy ? fy : 1.f - fy);
                    if (xi >= 0 && xi < Wl && yi >= 0 && yi < Hl) {
                        gsum += vbase[(size_t)(yi * Wl + xi) * D] * cw;
                    }
                }
            }
            acc += aww * gsum;
        }
    }
    SAMP[(size_t)r * D + h * HD + lane] = acc;
}

// ---------------- host launch ----------------
static inline dim3 gemm_grid(int M, int N) {
    return dim3((N + 127) / 128, (M + 127) / 128);
}

extern "C" void kernel_launch(void* const* d_in, const int* in_sizes, int n_in,
                              void* d_out, int out_size) {
    const float* tgt         = (const float*)d_in[0];
    const float* query_pos   = (const float*)d_in[1];
    const float* src         = (const float*)d_in[2];
    const float* in_proj_w   = (const float*)d_in[5];
    const float* in_proj_b   = (const float*)d_in[6];
    const float* out_proj_w  = (const float*)d_in[7];
    const float* out_proj_b  = (const float*)d_in[8];
    const float* samp_off_w  = (const float*)d_in[9];
    const float* samp_off_b  = (const float*)d_in[10];
    const float* attn_w_w    = (const float*)d_in[11];
    const float* attn_w_b    = (const float*)d_in[12];
    const float* value_proj_w= (const float*)d_in[13];
    const float* value_proj_b= (const float*)d_in[14];
    const float* cross_out_w = (const float*)d_in[15];
    const float* cross_out_b = (const float*)d_in[16];
    const float* ln1_g = (const float*)d_in[17];
    const float* ln1_b = (const float*)d_in[18];
    const float* ln2_g = (const float*)d_in[19];
    const float* ln2_b = (const float*)d_in[20];
    const float* ln3_g = (const float*)d_in[21];
    const float* ln3_b = (const float*)d_in[22];
    const float* ffn_w1 = (const float*)d_in[23];
    const float* ffn_b1 = (const float*)d_in[24];
    const float* ffn_w2 = (const float*)d_in[25];
    const float* ffn_b2 = (const float*)d_in[26];
    float* out = (float*)d_out;

    float *pQKV, *pCTX, *pT, *pTGT2, *pOFF, *pAW, *pVALUE, *pSAMP, *pTQ, *pHID, *pBIAS;
    cudaGetSymbolAddress((void**)&pQKV,  g_QKV);
    cudaGetSymbolAddress((void**)&pCTX,  g_CTX);
    cudaGetSymbolAddress((void**)&pT,    g_T);
    cudaGetSymbolAddress((void**)&pTGT2, g_TGT2);
    cudaGetSymbolAddress((void**)&pOFF,  g_OFF);
    cudaGetSymbolAddress((void**)&pAW,   g_AW);
    cudaGetSymbolAddress((void**)&pVALUE,g_VALUE);
    cudaGetSymbolAddress((void**)&pSAMP, g_SAMP);
    cudaGetSymbolAddress((void**)&pTQ,   g_TQ);
    cudaGetSymbolAddress((void**)&pHID,  g_HID);
    cudaGetSymbolAddress((void**)&pBIAS, g_BIAS);

    // 1. fold query_pos into Q/K, sampling-offset, attn-weight biases
    bias_fold_kernel<<<768 + 192 + 96, 256>>>(query_pos, in_proj_w, in_proj_b,
                                              samp_off_w, samp_off_b, attn_w_w, attn_w_b);
    // 2. QKV projection (pos folded into q,k biases)
    sgemm_bias_kernel<<<gemm_grid(M_ROWS, 3 * D), 256>>>(tgt, in_proj_w, pBIAS, pQKV,
                                                         M_ROWS, 3 * D, D, 0);
    // 3. self-attention (S=8)
    self_attn_kernel<<<LQ, 256>>>(pQKV, pCTX);
    // 4. attention out-proj
    sgemm_bias_kernel<<<gemm_grid(M_ROWS, D), 256>>>(pCTX, out_proj_w, out_proj_b, pTGT2,
                                                     M_ROWS, D, D, 0);
    // 5. t = LN2(tgt + tgt2)
    add_ln_kernel<<<M_ROWS, 256>>>(tgt, pTGT2, ln2_g, ln2_b, pT);
    // 6. sampling offsets (pos folded)
    sgemm_bias_kernel<<<gemm_grid(M_ROWS, NH * LEV * NP * 2), 256>>>(pT, samp_off_w, pBIAS + 768,
                                                                     pOFF, M_ROWS, NH * LEV * NP * 2, D, 0);
    // 7. attention weights (pos folded)
    sgemm_bias_kernel<<<gemm_grid(M_ROWS, NH * LEV * NP), 256>>>(pT, attn_w_w, pBIAS + 960,
                                                                 pAW, M_ROWS, NH * LEV * NP, D, 0);
    // 8. value projection
    sgemm_bias_kernel<<<gemm_grid(MV_ROWS, D), 256>>>(src, value_proj_w, value_proj_b, pVALUE,
                                                      MV_ROWS, D, D, 0);
    // 9. deformable sampling (fused aw softmax)
    msdeform_sample_kernel<<<M_ROWS, 256>>>(pOFF, pAW, pVALUE, pSAMP);
    // 10. cross-attn out-proj
    sgemm_bias_kernel<<<gemm_grid(M_ROWS, D), 256>>>(pSAMP, cross_out_w, cross_out_b, pTGT2,
                                                     M_ROWS, D, D, 0);
    // 11. tq = LN1(t + tgt2)
    add_ln_kernel<<<M_ROWS, 256>>>(pT, pTGT2, ln1_g, ln1_b, pTQ);
    // 12. FFN1 + ReLU
    sgemm_bias_kernel<<<gemm_grid(M_ROWS, DFF), 256>>>(pTQ, ffn_w1, ffn_b1, pHID,
                                                       M_ROWS, DFF, D, 1);
    // 13. FFN2
    sgemm_bias_kernel<<<gemm_grid(M_ROWS, D), 256>>>(pHID, ffn_w2, ffn_b2, pTGT2,
                                                     M_ROWS, D, DFF, 0);
    // 14. out = LN3(tq + ffn)
    add_ln_kernel<<<M_ROWS, 256>>>(pTQ, pTGT2, ln3_g, ln3_b, out);
}

// round 4
// speedup vs baseline: 1.6335x; 1.6335x over previous
#include <cuda_runtime.h>
#include <cuda_bf16.h>
#include <math.h>
#include <stdint.h>

// Problem constants
#define D 256
#define NH 8
#define HD 32
#define LEV 3
#define NP 4
#define DFF 1024
#define BATCH 8
#define LQ 3600
#define M_ROWS (LQ * BATCH)       // 28800
#define LIN 4725
#define MV_ROWS (BATCH * LIN)     // 37800

// ---------------- scratch (device globals; allocation-free) ----------------
__device__ float g_QKV[M_ROWS * 3 * D];
__device__ float g_CTX[M_ROWS * D];
__device__ float g_T[M_ROWS * D];
__device__ float g_TGT2[M_ROWS * D];
__device__ float g_OFF[M_ROWS * NH * LEV * NP * 2];
__device__ float g_AW[M_ROWS * NH * LEV * NP];
__device__ float g_VALUE[MV_ROWS * D];
__device__ float g_SAMP[M_ROWS * D];
__device__ float g_TQ[M_ROWS * D];
__device__ float g_HID[M_ROWS * DFF];
__device__ float g_BIAS[768 + 192 + 96];

// ---------------- tf32 mma.sync GEMM: C[M,N] = A[M,K] @ W[N,K]^T + bias ----
// CTA tile 128x128, BK=32, 256 threads = 8 warps (4 along M x 2 along N),
// warp tile 32x64 via m16n8k8 tf32 HMMA. SMEM padded [128][36] -> frag loads
// conflict-free (bank = 4*gid + tig covers 0..31).
#define AP 36

__device__ __forceinline__ uint32_t f2tf32(float f) {
    uint32_t u;
    asm("cvt.rna.tf32.f32 %0, %1;" : "=r"(u) : "f"(f));
    return u;
}

__device__ __forceinline__ void mma_tf32(float* c, uint32_t a0, uint32_t a1, uint32_t a2, uint32_t a3,
                                         uint32_t b0, uint32_t b1) {
    asm volatile("mma.sync.aligned.m16n8k8.row.col.f32.tf32.tf32.f32 "
                 "{%0,%1,%2,%3}, {%4,%5,%6,%7}, {%8,%9}, {%0,%1,%2,%3};"
                 : "+f"(c[0]), "+f"(c[1]), "+f"(c[2]), "+f"(c[3])
                 : "r"(a0), "r"(a1), "r"(a2), "r"(a3), "r"(b0), "r"(b1));
}

__global__ __launch_bounds__(256)
void tgemm_kernel(const float* __restrict__ A, const float* __restrict__ W,
                  const float* __restrict__ bias, float* __restrict__ C,
                  int M, int N, int K, int relu) {
    __shared__ float As[128 * AP];
    __shared__ float Bs[128 * AP];
    const int tid  = threadIdx.x;
    const int lane = tid & 31;
    const int wid  = tid >> 5;
    const int gid  = lane >> 2;     // 0..7
    const int tig  = lane & 3;      // 0..3
    const int wm   = (wid & 3) * 32;
    const int wn   = (wid >> 2) * 64;
    const int m0   = blockIdx.y * 128;
    const int n0   = blockIdx.x * 128;

    const int grow = tid >> 3;          // 0..31 -> row pair base (tid + i*256)>>3
    const int gc4  = (tid & 7) * 4;     // float4 col offset within 32-wide K tile

    float acc[2][8][4];
    #pragma unroll
    for (int i = 0; i < 2; i++)
        #pragma unroll
        for (int j = 0; j < 8; j++)
            #pragma unroll
            for (int r = 0; r < 4; r++) acc[i][j][r] = 0.f;

    const float4 zero = make_float4(0.f, 0.f, 0.f, 0.f);
    float4 pa[4], pb[4];

    // prefetch K-tile 0
    #pragma unroll
    for (int i = 0; i < 4; i++) {
        int row = grow + i * 32;
        int am = m0 + row, bn = n0 + row;
        pa[i] = (am < M) ? *reinterpret_cast<const float4*>(&A[(size_t)am * K + gc4]) : zero;
        pb[i] = (bn < N) ? *reinterpret_cast<const float4*>(&W[(size_t)bn * K + gc4]) : zero;
    }

    const int KT = K >> 5;
    for (int kt = 0; kt < KT; kt++) {
        // store prefetched tile to smem (with tf32 rounding)
        #pragma unroll
        for (int i = 0; i < 4; i++) {
            int row = grow + i * 32;
            uint4 ua, ub;
            ua.x = f2tf32(pa[i].x); ua.y = f2tf32(pa[i].y); ua.z = f2tf32(pa[i].z); ua.w = f2tf32(pa[i].w);
            ub.x = f2tf32(pb[i].x); ub.y = f2tf32(pb[i].y); ub.z = f2tf32(pb[i].z); ub.w = f2tf32(pb[i].w);
            *reinterpret_cast<uint4*>(&As[row * AP + gc4]) = ua;
            *reinterpret_cast<uint4*>(&Bs[row * AP + gc4]) = ub;
        }
        __syncthreads();

        // prefetch next K-tile
        if (kt + 1 < KT) {
            int k0 = (kt + 1) << 5;
            #pragma unroll
            for (int i = 0; i < 4; i++) {
                int row = grow + i * 32;
                int am = m0 + row, bn = n0 + row;
                pa[i] = (am < M) ? *reinterpret_cast<const float4*>(&A[(size_t)am * K + k0 + gc4]) : zero;
                pb[i] = (bn < N) ? *reinterpret_cast<const float4*>(&W[(size_t)bn * K + k0 + gc4]) : zero;
            }
        }

        // 4 k8-steps of HMMA
        const uint32_t* Au = reinterpret_cast<const uint32_t*>(As);
        const uint32_t* Bu = reinterpret_cast<const uint32_t*>(Bs);
        #pragma unroll
        for (int ks = 0; ks < 4; ks++) {
            const int kk = ks * 8;
            uint32_t af[2][4];
            #pragma unroll
            for (int mt = 0; mt < 2; mt++) {
                int rbase = (wm + mt * 16 + gid) * AP + kk + tig;
                af[mt][0] = Au[rbase];
                af[mt][1] = Au[rbase + 8 * AP];
                af[mt][2] = Au[rbase + 4];
                af[mt][3] = Au[rbase + 8 * AP + 4];
            }
            #pragma unroll
            for (int nt = 0; nt < 8; nt++) {
                int rbase = (wn + nt * 8 + gid) * AP + kk + tig;
                uint32_t b0 = Bu[rbase];
                uint32_t b1 = Bu[rbase + 4];
                #pragma unroll
                for (int mt = 0; mt < 2; mt++)
                    mma_tf32(acc[mt][nt], af[mt][0], af[mt][1], af[mt][2], af[mt][3], b0, b1);
            }
        }
        __syncthreads();
    }

    // epilogue: bias (+relu), float2 stores
    #pragma unroll
    for (int mt = 0; mt < 2; mt++) {
        #pragma unroll
        for (int half = 0; half < 2; half++) {
            int m = m0 + wm + mt * 16 + gid + half * 8;
            if (m >= M) continue;
            #pragma unroll
            for (int nt = 0; nt < 8; nt++) {
                int n = n0 + wn + nt * 8 + tig * 2;
                if (n >= N) continue;
                float v0 = acc[mt][nt][half * 2 + 0] + bias[n];
                float v1 = acc[mt][nt][half * 2 + 1] + bias[n + 1];
                if (relu) { v0 = fmaxf(v0, 0.f); v1 = fmaxf(v1, 0.f); }
                *reinterpret_cast<float2*>(&C[(size_t)m * N + n]) = make_float2(v0, v1);
            }
        }
    }
}

// ---------------- bias folding: b' = b + pos @ W^T ----------------
__global__ void bias_fold_kernel(const float* __restrict__ pos,
                                 const float* __restrict__ Wqkv, const float* __restrict__ bqkv,
                                 const float* __restrict__ Wso,  const float* __restrict__ bso,
                                 const float* __restrict__ Waw,  const float* __restrict__ baw) {
    int i = blockIdx.x, t = threadIdx.x;
    const float* wrow = nullptr; float bb;
    if (i < 768)      { bb = bqkv[i]; if (i < 512) wrow = Wqkv + (size_t)i * D; }
    else if (i < 960) { int j = i - 768; bb = bso[j]; wrow = Wso + (size_t)j * D; }
    else              { int j = i - 960; bb = baw[j]; wrow = Waw + (size_t)j * D; }
    float p = wrow ? pos[t] * wrow[t] : 0.f;
    #pragma unroll
    for (int m = 16; m; m >>= 1) p += __shfl_xor_sync(0xffffffffu, p, m);
    __shared__ float sh[8];
    if ((t & 31) == 0) sh[t >> 5] = p;
    __syncthreads();
    if (t == 0) {
        float s = 0.f;
        #pragma unroll
        for (int w = 0; w < 8; w++) s += sh[w];
        g_BIAS[i] = bb + s;
    }
}

// ---------------- tiny self-attention over S=8 ----------------
__global__ __launch_bounds__(256)
void self_attn_kernel(const float* __restrict__ QKV, float* __restrict__ CTX) {
    int n = blockIdx.x;
    int h = threadIdx.x >> 5, lane = threadIdx.x & 31;
    const float* base = QKV + (size_t)n * 8 * (3 * D) + h * HD + lane;
    float q[8], k[8], v[8];
    #pragma unroll
    for (int s = 0; s < 8; s++) {
        q[s] = base[s * 3 * D];
        k[s] = base[s * 3 * D + D];
        v[s] = base[s * 3 * D + 2 * D];
    }
    const float scale = rsqrtf((float)HD);
    #pragma unroll
    for (int s = 0; s < 8; s++) {
        float lg[8];
        #pragma unroll
        for (int t = 0; t < 8; t++) {
            float p = q[s] * k[t];
            #pragma unroll
            for (int m = 16; m; m >>= 1) p += __shfl_xor_sync(0xffffffffu, p, m);
            lg[t] = p * scale;
        }
        float mx = lg[0];
        #pragma unroll
        for (int t = 1; t < 8; t++) mx = fmaxf(mx, lg[t]);
        float sum = 0.f, e[8];
        #pragma unroll
        for (int t = 0; t < 8; t++) { e[t] = __expf(lg[t] - mx); sum += e[t]; }
        float inv = 1.f / sum;
        float c = 0.f;
        #pragma unroll
        for (int t = 0; t < 8; t++) c += e[t] * v[t];
        c *= inv;
        CTX[(size_t)(n * 8 + s) * D + h * HD + lane] = c;
    }
}

// ---------------- residual + LayerNorm ----------------
__global__ __launch_bounds__(256)
void add_ln_kernel(const float* __restrict__ A, const float* __restrict__ Bv,
                   const float* __restrict__ g, const float* __restrict__ be,
                   float* __restrict__ out) {
    int r = blockIdx.x, d = threadIdx.x;
    size_t idx = (size_t)r * D + d;
    float x = A[idx] + Bv[idx];
    __shared__ float sh[8];
    __shared__ float s_mean, s_var;
    float p = x;
    #pragma unroll
    for (int m = 16; m; m >>= 1) p += __shfl_xor_sync(0xffffffffu, p, m);
    if ((d & 31) == 0) sh[d >> 5] = p;
    __syncthreads();
    if (d == 0) {
        float s = 0.f;
        #pragma unroll
        for (int w = 0; w < 8; w++) s += sh[w];
        s_mean = s * (1.f / D);
    }
    __syncthreads();
    float xm = x - s_mean;
    p = xm * xm;
    #pragma unroll
    for (int m = 16; m; m >>= 1) p += __shfl_xor_sync(0xffffffffu, p, m);
    __syncthreads();
    if ((d & 31) == 0) sh[d >> 5] = p;
    __syncthreads();
    if (d == 0) {
        float s = 0.f;
        #pragma unroll
        for (int w = 0; w < 8; w++) s += sh[w];
        s_var = s * (1.f / D);
    }
    __syncthreads();
    out[idx] = xm * rsqrtf(s_var + 1e-5f) * g[d] + be[d];
}

// ---------------- MS-deformable sampling (fused aw-softmax) ----------------
__global__ __launch_bounds__(256)
void msdeform_sample_kernel(const float* __restrict__ OFF, const float* __restrict__ AW,
                            const float* __restrict__ VALUE, float* __restrict__ SAMP) {
    int r = blockIdx.x;
    int h = threadIdx.x >> 5, lane = threadIdx.x & 31;
    int l = r >> 3, b = r & 7;
    float refx = ((float)(l % 60) + 0.5f) / 60.f;
    float refy = ((float)(l / 60) + 0.5f) / 60.f;

    const float* awp = AW + (size_t)r * (NH * LEV * NP) + h * (LEV * NP);
    float w[LEV * NP];
    float mx = -1e30f;
    #pragma unroll
    for (int i = 0; i < LEV * NP; i++) { w[i] = awp[i]; mx = fmaxf(mx, w[i]); }
    float s = 0.f;
    #pragma unroll
    for (int i = 0; i < LEV * NP; i++) { w[i] = __expf(w[i] - mx); s += w[i]; }
    float inv = 1.f / s;

    const float* offp = OFF + (size_t)r * (NH * LEV * NP * 2) + h * (LEV * NP * 2);
    const int Hs[LEV] = {60, 30, 15};
    const int Ss[LEV] = {0, 3600, 4500};

    float acc = 0.f;
    #pragma unroll
    for (int lev = 0; lev < LEV; lev++) {
        const int Hl = Hs[lev], Wl = Hs[lev];
        const float* vbase = VALUE + ((size_t)b * LIN + Ss[lev]) * D + h * HD + lane;
        #pragma unroll
        for (int p = 0; p < NP; p++) {
            float ox = offp[lev * (NP * 2) + p * 2 + 0];
            float oy = offp[lev * (NP * 2) + p * 2 + 1];
            float x = (refx + ox / (float)Wl) * (float)Wl - 0.5f;
            float y = (refy + oy / (float)Hl) * (float)Hl - 0.5f;
            float x0f = floorf(x), y0f = floorf(y);
            float fx = x - x0f, fy = y - y0f;
            int x0 = (int)x0f, y0 = (int)y0f;
            float aww = w[lev * NP + p] * inv;
            float gsum = 0.f;
            #pragma unroll
            for (int cy = 0; cy < 2; cy++) {
                #pragma unroll
                for (int cx = 0; cx < 2; cx++) {
                    int xi = x0 + cx, yi = y0 + cy;
                    float cw = (cx ? fx : 1.f - fx) * (cy ? fy : 1.f - fy);
                    if (xi >= 0 && xi < Wl && yi >= 0 && yi < Hl) {
                        gsum += vbase[(size_t)(yi * Wl + xi) * D] * cw;
                    }
                }
            }
            acc += aww * gsum;
        }
    }
    SAMP[(size_t)r * D + h * HD + lane] = acc;
}

// ---------------- host launch ----------------
static inline dim3 tgrid(int M, int N) {
    return dim3((N + 127) / 128, (M + 127) / 128);
}
static void tgemm(const float* A, const float* W, const float* bias, float* C,
                  int M, int N, int K, int relu) {
    tgemm_kernel<<<tgrid(M, N), 256>>>(A, W, bias, C, M, N, K, relu);
}

extern "C" void kernel_launch(void* const* d_in, const int* in_sizes, int n_in,
                              void* d_out, int out_size) {
    const float* tgt         = (const float*)d_in[0];
    const float* query_pos   = (const float*)d_in[1];
    const float* src         = (const float*)d_in[2];
    const float* in_proj_w   = (const float*)d_in[5];
    const float* in_proj_b   = (const float*)d_in[6];
    const float* out_proj_w  = (const float*)d_in[7];
    const float* out_proj_b  = (const float*)d_in[8];
    const float* samp_off_w  = (const float*)d_in[9];
    const float* samp_off_b  = (const float*)d_in[10];
    const float* attn_w_w    = (const float*)d_in[11];
    const float* attn_w_b    = (const float*)d_in[12];
    const float* value_proj_w= (const float*)d_in[13];
    const float* value_proj_b= (const float*)d_in[14];
    const float* cross_out_w = (const float*)d_in[15];
    const float* cross_out_b = (const float*)d_in[16];
    const float* ln1_g = (const float*)d_in[17];
    const float* ln1_b = (const float*)d_in[18];
    const float* ln2_g = (const float*)d_in[19];
    const float* ln2_b = (const float*)d_in[20];
    const float* ln3_g = (const float*)d_in[21];
    const float* ln3_b = (const float*)d_in[22];
    const float* ffn_w1 = (const float*)d_in[23];
    const float* ffn_b1 = (const float*)d_in[24];
    const float* ffn_w2 = (const float*)d_in[25];
    const float* ffn_b2 = (const float*)d_in[26];
    float* out = (float*)d_out;

    float *pQKV, *pCTX, *pT, *pTGT2, *pOFF, *pAW, *pVALUE, *pSAMP, *pTQ, *pHID, *pBIAS;
    cudaGetSymbolAddress((void**)&pQKV,  g_QKV);
    cudaGetSymbolAddress((void**)&pCTX,  g_CTX);
    cudaGetSymbolAddress((void**)&pT,    g_T);
    cudaGetSymbolAddress((void**)&pTGT2, g_TGT2);
    cudaGetSymbolAddress((void**)&pOFF,  g_OFF);
    cudaGetSymbolAddress((void**)&pAW,   g_AW);
    cudaGetSymbolAddress((void**)&pVALUE,g_VALUE);
    cudaGetSymbolAddress((void**)&pSAMP, g_SAMP);
    cudaGetSymbolAddress((void**)&pTQ,   g_TQ);
    cudaGetSymbolAddress((void**)&pHID,  g_HID);
    cudaGetSymbolAddress((void**)&pBIAS, g_BIAS);

    // 1. fold query_pos into Q/K, sampling-offset, attn-weight biases
    bias_fold_kernel<<<768 + 192 + 96, 256>>>(query_pos, in_proj_w, in_proj_b,
                                              samp_off_w, samp_off_b, attn_w_w, attn_w_b);
    // 2. QKV projection (pos folded into q,k biases)
    tgemm(tgt, in_proj_w, pBIAS, pQKV, M_ROWS, 3 * D, D, 0);
    // 3. self-attention (S=8)
    self_attn_kernel<<<LQ, 256>>>(pQKV, pCTX);
    // 4. attention out-proj
    tgemm(pCTX, out_proj_w, out_proj_b, pTGT2, M_ROWS, D, D, 0);
    // 5. t = LN2(tgt + tgt2)
    add_ln_kernel<<<M_ROWS, 256>>>(tgt, pTGT2, ln2_g, ln2_b, pT);
    // 6. sampling offsets (pos folded)
    tgemm(pT, samp_off_w, pBIAS + 768, pOFF, M_ROWS, NH * LEV * NP * 2, D, 0);
    // 7. attention weights (pos folded)
    tgemm(pT, attn_w_w, pBIAS + 960, pAW, M_ROWS, NH * LEV * NP, D, 0);
    // 8. value projection
    tgemm(src, value_proj_w, value_proj_b, pVALUE, MV_ROWS, D, D, 0);
    // 9. deformable sampling (fused aw softmax)
    msdeform_sample_kernel<<<M_ROWS, 256>>>(pOFF, pAW, pVALUE, pSAMP);
    // 10. cross-attn out-proj
    tgemm(pSAMP, cross_out_w, cross_out_b, pTGT2, M_ROWS, D, D, 0);
    // 11. tq = LN1(t + tgt2)
    add_ln_kernel<<<M_ROWS, 256>>>(pT, pTGT2, ln1_g, ln1_b, pTQ);
    // 12. FFN1 + ReLU
    tgemm(pTQ, ffn_w1, ffn_b1, pHID, M_ROWS, DFF, D, 1);
    // 13. FFN2
    tgemm(pHID, ffn_w2, ffn_b2, pTGT2, M_ROWS, D, DFF, 0);
    // 14. out = LN3(tq + ffn)
    add_ln_kernel<<<M_ROWS, 256>>>(pTQ, pTGT2, ln3_g, ln3_b, out);
}